// round 1
// baseline (speedup 1.0000x reference)
#include <cuda_runtime.h>

#define NB 8
#define NC 3
#define NH 512
#define NW 512
#define HP 514
#define WP 514
#define BX 32
#define BY 8

// Scratch (no cudaMalloc allowed)
__device__ float g_imgp[NB * NC * HP * WP]; // padded img + noise
__device__ float g_imgr[NB * NH * NW];      // guided average
__device__ float g_mod [NB * NH * NW];      // selected weight element

// ---------------------------------------------------------------------------
// K0: img_p = pad(img, 1) + noise   [B,C,514,514]
// ---------------------------------------------------------------------------
__global__ __launch_bounds__(256) void k0_pad(
    const float* __restrict__ img, const float* __restrict__ noise,
    const int* __restrict__ sel)
{
    int idx = blockIdx.x * 256 + threadIdx.x;
    const int per_b = NC * HP * WP;
    const int total = NB * per_b;
    if (idx >= total) return;
    int b = idx / per_b;
    if (!sel[b]) return;                    // img_p unused for non-selected batches
    int rem = idx - b * per_b;
    int c  = rem / (HP * WP);
    int yx = rem - c * (HP * WP);
    int y = yx / WP, x = yx - y * WP;
    float v = noise[idx];
    if (y >= 1 && y <= NH && x >= 1 && x <= NW)
        v += img[(((b * NC + c) * NH) + (y - 1)) * NW + (x - 1)];
    g_imgp[idx] = v;
}

// ---------------------------------------------------------------------------
// K1: per pixel: window stats per channel -> z = (x-mean)^2/(2 var),
//     m[k] = exp(-max_c z_c[k])  (== min_c of the gaussian weights),
//     img_r = sum_{c,k} x*m / sum_k m
// ---------------------------------------------------------------------------
__global__ __launch_bounds__(BX * BY) void k1_imgr(const int* __restrict__ sel)
{
    int b = blockIdx.z;
    if (!sel[b]) return;
    int bx = blockIdx.x * BX, by = blockIdx.y * BY;
    __shared__ float sp[NC][BY + 2][BX + 2];
    int tid = threadIdx.y * BX + threadIdx.x;
    const int TS = (BY + 2) * (BX + 2); // 340
    for (int i = tid; i < NC * TS; i += BX * BY) {
        int c = i / TS, r = (i % TS) / (BX + 2), col = i % (BX + 2);
        sp[c][r][col] = g_imgp[(((b * NC + c) * HP) + by + r) * WP + bx + col];
    }
    __syncthreads();

    int tx = threadIdx.x, ty = threadIdx.y;
    float v[NC][9];
    float zmax[9];
    #pragma unroll
    for (int c = 0; c < NC; c++) {
        float s = 0.f, ss = 0.f;
        #pragma unroll
        for (int i = 0; i < 3; i++)
            #pragma unroll
            for (int j = 0; j < 3; j++) {
                float x = sp[c][ty + i][tx + j];
                v[c][i * 3 + j] = x;
                s += x;
                ss = fmaf(x, x, ss);
            }
        float mean = s * (1.f / 9.f);
        float var  = (ss - s * mean) * (1.f / 8.f); // unbiased (ddof=1)
        float a    = 0.5f / var;                    // 1/(2 var)
        #pragma unroll
        for (int k = 0; k < 9; k++) {
            float d = v[c][k] - mean;
            float z = d * d * a;
            zmax[k] = (c == 0) ? z : fmaxf(zmax[k], z);
        }
    }
    float m[9], den = 0.f, num = 0.f;
    #pragma unroll
    for (int k = 0; k < 9; k++) { m[k] = __expf(-zmax[k]); den += m[k]; }
    #pragma unroll
    for (int c = 0; c < NC; c++)
        #pragma unroll
        for (int k = 0; k < 9; k++) num = fmaf(v[c][k], m[k], num);
    g_imgr[(b * NH + by + ty) * NW + bx + tx] = num / den;
}

// ---------------------------------------------------------------------------
// K2: argmin/argmax over zero-padded 3x3 img_r window (first-occurrence ties),
//     select index by mix_sel, recompute that element of img_3d at the center.
// ---------------------------------------------------------------------------
__global__ __launch_bounds__(BX * BY) void k2_mod(
    const int* __restrict__ sel, const int* __restrict__ mixsel)
{
    int b = blockIdx.z;
    if (!sel[b]) return;
    int bx = blockIdx.x * BX, by = blockIdx.y * BY;
    __shared__ float sp[NC][BY + 2][BX + 2];
    __shared__ float sr[BY + 2][BX + 2];
    int tid = threadIdx.y * BX + threadIdx.x;
    const int TS = (BY + 2) * (BX + 2);
    for (int i = tid; i < NC * TS; i += BX * BY) {
        int c = i / TS, r = (i % TS) / (BX + 2), col = i % (BX + 2);
        sp[c][r][col] = g_imgp[(((b * NC + c) * HP) + by + r) * WP + bx + col];
    }
    for (int i = tid; i < TS; i += BX * BY) {
        int r = i / (BX + 2), col = i % (BX + 2);
        int gy = by + r - 1, gx = bx + col - 1;
        float val = 0.f; // zero padding of img_r
        if (gy >= 0 && gy < NH && gx >= 0 && gx < NW)
            val = g_imgr[(b * NH + gy) * NW + gx];
        sr[r][col] = val;
    }
    __syncthreads();

    int tx = threadIdx.x, ty = threadIdx.y;
    float vmin = sr[ty][tx], vmax = vmin;
    int imin = 0, imax = 0;
    #pragma unroll
    for (int k = 1; k < 9; k++) {
        float r = sr[ty + k / 3][tx + k % 3];
        if (r < vmin) { vmin = r; imin = k; } // strict: first-occurrence ties
        if (r > vmax) { vmax = r; imax = k; }
    }
    int ids = mixsel[b] ? imax : imin;
    int ki = ids / 3, kj = ids % 3;

    float zm = 0.f; // z >= 0 always, so 0 is a safe identity for max
    #pragma unroll
    for (int c = 0; c < NC; c++) {
        float s = 0.f, ss = 0.f;
        #pragma unroll
        for (int i = 0; i < 3; i++)
            #pragma unroll
            for (int j = 0; j < 3; j++) {
                float x = sp[c][ty + i][tx + j];
                s += x;
                ss = fmaf(x, x, ss);
            }
        float mean = s * (1.f / 9.f);
        float var  = (ss - s * mean) * (1.f / 8.f);
        float a    = 0.5f / var;
        float d    = sp[c][ty + ki][tx + kj] - mean;
        zm = fmaxf(zm, d * d * a);
    }
    g_mod[(b * NH + by + ty) * NW + bx + tx] = __expf(-zm);
}

// ---------------------------------------------------------------------------
// K3: img_mod[c] = sum_k img_e[c,k]*m_e[k] / sum_k m_e[k]  (m_e zero-padded),
//     out = sel ? img_mod*(1-re) + img*re : img
// ---------------------------------------------------------------------------
__global__ __launch_bounds__(BX * BY) void k3_out(
    const float* __restrict__ img, const float* __restrict__ re,
    const int* __restrict__ sel, float* __restrict__ out)
{
    int b = blockIdx.z;
    int bx = blockIdx.x * BX, by = blockIdx.y * BY;
    int tx = threadIdx.x, ty = threadIdx.y;
    int h = by + ty, w = bx + tx;

    if (!sel[b]) { // pure copy path (entire block uniform, safe early return)
        #pragma unroll
        for (int c = 0; c < NC; c++) {
            int gi = (((b * NC + c) * NH) + h) * NW + w;
            out[gi] = img[gi];
        }
        return;
    }

    __shared__ float sp[NC][BY + 2][BX + 2];
    __shared__ float sm[BY + 2][BX + 2];
    int tid = ty * BX + tx;
    const int TS = (BY + 2) * (BX + 2);
    for (int i = tid; i < NC * TS; i += BX * BY) {
        int c = i / TS, r = (i % TS) / (BX + 2), col = i % (BX + 2);
        sp[c][r][col] = g_imgp[(((b * NC + c) * HP) + by + r) * WP + bx + col];
    }
    for (int i = tid; i < TS; i += BX * BY) {
        int r = i / (BX + 2), col = i % (BX + 2);
        int gy = by + r - 1, gx = bx + col - 1;
        float val = 0.f; // zero padding of img_3d_mod
        if (gy >= 0 && gy < NH && gx >= 0 && gx < NW)
            val = g_mod[(b * NH + gy) * NW + gx];
        sm[r][col] = val;
    }
    __syncthreads();

    float mk[9], den = 0.f;
    #pragma unroll
    for (int k = 0; k < 9; k++) {
        mk[k] = sm[ty + k / 3][tx + k % 3];
        den += mk[k];
    }
    #pragma unroll
    for (int c = 0; c < NC; c++) {
        float num = 0.f;
        #pragma unroll
        for (int k = 0; k < 9; k++)
            num = fmaf(sp[c][ty + k / 3][tx + k % 3], mk[k], num);
        float mod = num / den;
        int gi = (((b * NC + c) * NH) + h) * NW + w;
        float r  = re[gi];
        float im = img[gi];
        out[gi] = mod * (1.f - r) + im * r;
    }
}

// ---------------------------------------------------------------------------
extern "C" void kernel_launch(void* const* d_in, const int* in_sizes, int n_in,
                              void* d_out, int out_size)
{
    const float* img    = (const float*)d_in[0];
    const float* noise  = (const float*)d_in[1];
    const float* re     = (const float*)d_in[2];
    const int*   sel    = (const int*)d_in[3];
    const int*   mixsel = (const int*)d_in[4];
    float*       out    = (float*)d_out;

    {
        int total = NB * NC * HP * WP;
        k0_pad<<<(total + 255) / 256, 256>>>(img, noise, sel);
    }
    dim3 blk(BX, BY), grd(NW / BX, NH / BY, NB);
    k1_imgr<<<grd, blk>>>(sel);
    k2_mod<<<grd, blk>>>(sel, mixsel);
    k3_out<<<grd, blk>>>(img, re, sel, out);
}

// round 2
// speedup vs baseline: 1.3409x; 1.3409x over previous
#include <cuda_runtime.h>

#define NB 8
#define NC 3
#define NH 512
#define NW 512
#define HP 514
#define WP 514
#define BX 32
#define BY 16
#define NT (BX * BY)          // 512 threads

// shared tile dims
#define TX (BX + 6)           // 38  img_p cols (radius 3)
#define TY (BY + 6)           // 22  img_p rows
#define RX (BX + 4)           // 36  img_r cols (radius 2)
#define RY (BY + 4)           // 20
#define MX (BX + 2)           // 34  mod cols (radius 1)
#define MY (BY + 2)           // 18

__global__ __launch_bounds__(NT) void gdfn_fused(
    const float* __restrict__ img, const float* __restrict__ noise,
    const float* __restrict__ re, const int* __restrict__ sel,
    const int* __restrict__ mixsel, float* __restrict__ out)
{
    const int b  = blockIdx.z;
    const int bx = blockIdx.x * BX;
    const int by = blockIdx.y * BY;
    const int tx = threadIdx.x, ty = threadIdx.y;
    const int tid = ty * BX + tx;
    const int h = by + ty, w = bx + tx;

    if (!sel[b]) {  // uniform early-exit: pure copy
        #pragma unroll
        for (int c = 0; c < NC; c++) {
            int gi = (((b * NC + c) * NH) + h) * NW + w;
            out[gi] = img[gi];
        }
        return;
    }

    __shared__ float sp[NC][TY][TX];      // img_p tile (pad(img)+noise)
    __shared__ float sr[RY][RX];          // img_r (zero outside image)
    __shared__ float sstat[2 * NC][RY][RX]; // mean[c], a[c]=0.5/var per img_r pixel
    __shared__ float sm[MY][MX];          // img_3d_mod (zero outside image)

    const int yo = by - 2;  // sp origin in img_p coords (img_p row = img row + 1... see below)
    const int xo = bx - 2;
    // Convention: img pixel (h,w) window = img_p[h..h+2, w..w+2] (img_p coords 0..513).
    // sp[c][ly][lx] = img_p[yo+ly][xo+lx]

    // ---- load img_p tile ----
    for (int i = tid; i < NC * TY * TX; i += NT) {
        int c  = i / (TY * TX);
        int rm = i - c * (TY * TX);
        int ly = rm / TX, lx = rm - ly * TX;
        int yp = yo + ly, xp = xo + lx;
        float v = 0.f;
        if (yp >= 0 && yp < HP && xp >= 0 && xp < WP) {
            v = noise[(((b * NC + c) * HP) + yp) * WP + xp];
            if (yp >= 1 && yp <= NH && xp >= 1 && xp <= NW)
                v += img[(((b * NC + c) * NH) + (yp - 1)) * NW + (xp - 1)];
        }
        sp[c][ly][lx] = v;
    }
    __syncthreads();

    // ---- stage A: img_r + per-channel stats on (RY x RX) region ----
    for (int i = tid; i < RY * RX; i += NT) {
        int ly2 = i / RX, lx2 = i - ly2 * RX;
        int hh = by - 2 + ly2, ww = bx - 2 + lx2;
        float rv = 0.f;
        if (hh >= 0 && hh < NH && ww >= 0 && ww < NW) {
            float v[NC][9];
            float zmax[9];
            #pragma unroll
            for (int c = 0; c < NC; c++) {
                float s = 0.f, ss = 0.f;
                #pragma unroll
                for (int ki = 0; ki < 3; ki++)
                    #pragma unroll
                    for (int kj = 0; kj < 3; kj++) {
                        float x = sp[c][ly2 + ki][lx2 + kj];
                        v[c][ki * 3 + kj] = x;
                        s += x;
                        ss = fmaf(x, x, ss);
                    }
                float mean = s * (1.f / 9.f);
                float var  = (ss - s * mean) * (1.f / 8.f);  // ddof=1
                float a    = 0.5f / var;
                sstat[c][ly2][lx2]      = mean;
                sstat[NC + c][ly2][lx2] = a;
                #pragma unroll
                for (int k = 0; k < 9; k++) {
                    float d = v[c][k] - mean;
                    float z = d * d * a;
                    zmax[k] = (c == 0) ? z : fmaxf(zmax[k], z);
                }
            }
            float num = 0.f, den = 0.f;
            #pragma unroll
            for (int k = 0; k < 9; k++) {
                float m = __expf(-zmax[k]);
                den += m;
                num = fmaf(v[0][k] + 0.f, m, num);  // c=0 part
                num = fmaf(v[1][k], m, num);
                num = fmaf(v[2][k], m, num);
            }
            rv = num / den;
        }
        sr[ly2][lx2] = rv;
    }
    __syncthreads();

    // ---- stage B: mod on (MY x MX) region ----
    for (int i = tid; i < MY * MX; i += NT) {
        int ly3 = i / MX, lx3 = i - ly3 * MX;
        int hh = by - 1 + ly3, ww = bx - 1 + lx3;
        float mv = 0.f;
        if (hh >= 0 && hh < NH && ww >= 0 && ww < NW) {
            // argmin/argmax over zero-padded img_r 3x3 (first-occurrence ties)
            float vmin = sr[ly3][lx3], vmax = vmin;
            int imin = 0, imax = 0;
            #pragma unroll
            for (int k = 1; k < 9; k++) {
                float r = sr[ly3 + k / 3][lx3 + k % 3];
                if (r < vmin) { vmin = r; imin = k; }
                if (r > vmax) { vmax = r; imax = k; }
            }
            int ids = mixsel[b] ? imax : imin;
            int ki = ids / 3, kj = ids % 3;
            // z at selected window element, max over channels
            float zm = 0.f;
            #pragma unroll
            for (int c = 0; c < NC; c++) {
                float mean = sstat[c][ly3 + 1][lx3 + 1];
                float a    = sstat[NC + c][ly3 + 1][lx3 + 1];
                float d    = sp[c][ly3 + 1 + ki][lx3 + 1 + kj] - mean;
                zm = fmaxf(zm, d * d * a);
            }
            mv = __expf(-zm);
        }
        sm[ly3][lx3] = mv;
    }
    __syncthreads();

    // ---- stage C: final weighted average + blend ----
    float mk[9], den = 0.f;
    #pragma unroll
    for (int k = 0; k < 9; k++) {
        mk[k] = sm[ty + k / 3][tx + k % 3];
        den += mk[k];
    }
    float inv_den = 1.f / den;
    #pragma unroll
    for (int c = 0; c < NC; c++) {
        float num = 0.f;
        #pragma unroll
        for (int k = 0; k < 9; k++)
            num = fmaf(sp[c][ty + 2 + k / 3][tx + 2 + k % 3], mk[k], num);
        float mod = num * inv_den;
        int gi = (((b * NC + c) * NH) + h) * NW + w;
        float r  = re[gi];
        out[gi] = mod * (1.f - r) + img[gi] * r;
    }
}

extern "C" void kernel_launch(void* const* d_in, const int* in_sizes, int n_in,
                              void* d_out, int out_size)
{
    const float* img    = (const float*)d_in[0];
    const float* noise  = (const float*)d_in[1];
    const float* re     = (const float*)d_in[2];
    const int*   sel    = (const int*)d_in[3];
    const int*   mixsel = (const int*)d_in[4];
    float*       out    = (float*)d_out;

    dim3 blk(BX, BY), grd(NW / BX, NH / BY, NB);
    gdfn_fused<<<grd, blk>>>(img, noise, re, sel, mixsel, out);
}

// round 4
// speedup vs baseline: 1.7016x; 1.2690x over previous
#include <cuda_runtime.h>

#define NB 8
#define NC 3
#define NH 512
#define NW 512
#define HP 514
#define WP 514
#define BX 32
#define BY 16
#define NT (BX * BY)          // 512 threads

// shared tile dims
#define TX (BX + 6)           // 38  img_p cols (radius 3)
#define TY (BY + 6)           // 22  img_p rows
#define RX (BX + 4)           // 36  img_r cols (radius 2)
#define RY (BY + 4)           // 20
#define MX (BX + 2)           // 34  mod cols (radius 1)
#define MY (BY + 2)           // 18

struct Smem {
    float sp[NC][TY][TX];        // img_p tile
    float sr[RY][RX];            // img_r (zero outside image)
    float smean[NC][RY][RX];     // per-channel window mean
    float sa[NC][RY][RX];        // per-channel 0.5/var
    float sm[MY][MX];            // img_3d_mod (zero outside image)
};

// stage A: one img_r pixel + its stats
static __device__ __forceinline__ void stageA(Smem& S, int i, int by, int bx)
{
    int ly = i / RX, lx = i - ly * RX;
    int hh = by - 2 + ly, ww = bx - 2 + lx;
    float rv = 0.f;
    if (hh >= 0 && hh < NH && ww >= 0 && ww < NW) {
        float zmax[9], u[9];
        #pragma unroll
        for (int c = 0; c < NC; c++) {
            float x[9];
            float s = 0.f, ss = 0.f;
            #pragma unroll
            for (int k = 0; k < 9; k++) {
                x[k] = S.sp[c][ly + k / 3][lx + k % 3];
                s += x[k];
                ss = fmaf(x[k], x[k], ss);
            }
            float mean = s * (1.f / 9.f);
            float a    = __fdividef(4.f, fmaf(-s, mean, ss)); // 0.5/var, ddof=1
            S.smean[c][ly][lx] = mean;
            S.sa[c][ly][lx]    = a;
            #pragma unroll
            for (int k = 0; k < 9; k++) {
                float d = x[k] - mean;
                float z = d * d * a;
                if (c == 0) { zmax[k] = z; u[k] = x[k]; }
                else        { zmax[k] = fmaxf(zmax[k], z); u[k] += x[k]; }
            }
        }
        float num = 0.f, den = 0.f;
        #pragma unroll
        for (int k = 0; k < 9; k++) {
            float m = __expf(-zmax[k]);
            den += m;
            num = fmaf(u[k], m, num);
        }
        rv = __fdividef(num, den);
    }
    S.sr[ly][lx] = rv;
}

// stage B: one mod pixel
static __device__ __forceinline__ void stageB(Smem& S, int i, int by, int bx, int mix)
{
    int ly = i / MX, lx = i - ly * MX;
    int hh = by - 1 + ly, ww = bx - 1 + lx;
    float mv = 0.f;
    if (hh >= 0 && hh < NH && ww >= 0 && ww < NW) {
        float vmin = S.sr[ly][lx], vmax = vmin;
        int imin = 0, imax = 0;
        #pragma unroll
        for (int k = 1; k < 9; k++) {
            float r = S.sr[ly + k / 3][lx + k % 3];
            if (r < vmin) { vmin = r; imin = k; }   // first-occurrence ties
            if (r > vmax) { vmax = r; imax = k; }
        }
        int ids = mix ? imax : imin;
        int ki = ids / 3, kj = ids % 3;
        float zm = 0.f;
        #pragma unroll
        for (int c = 0; c < NC; c++) {
            float mean = S.smean[c][ly + 1][lx + 1];
            float a    = S.sa[c][ly + 1][lx + 1];
            float d    = S.sp[c][ly + 1 + ki][lx + 1 + kj] - mean;
            zm = fmaxf(zm, d * d * a);
        }
        mv = __expf(-zm);
    }
    S.sm[ly][lx] = mv;
}

__global__ __launch_bounds__(NT, 3) void gdfn_fused(
    const float* __restrict__ img, const float* __restrict__ noise,
    const float* __restrict__ re, const int* __restrict__ sel,
    const int* __restrict__ mixsel, float* __restrict__ out)
{
    const int b  = blockIdx.z;
    const int bx = blockIdx.x * BX;
    const int by = blockIdx.y * BY;
    const int tx = threadIdx.x, ty = threadIdx.y;
    const int tid = ty * BX + tx;
    const int h = by + ty, w = bx + tx;

    if (!sel[b]) {  // uniform early-exit: pure copy
        #pragma unroll
        for (int c = 0; c < NC; c++) {
            int gi = (((b * NC + c) * NH) + h) * NW + w;
            out[gi] = img[gi];
        }
        return;
    }

    __shared__ Smem S;
    const int mix = mixsel[b];

    // ---- load img_p tile: sp[c][ly][lx] = img_p[by-2+ly][bx-2+lx] ----
    const int yo = by - 2, xo = bx - 2;
    const bool interior = (by >= 3) && (by + 19 <= NH - 1 + 3) && (bx >= 3) && (bx + 35 <= 513 - 2);
    // interior <=> all yp in [1,NH], xp in [1,NW]
    if ((by >= 3) && (by + TY - 3 <= NH) && (bx >= 3) && (bx + TX - 3 <= NW)) {
        for (int i = tid; i < NC * TY * TX; i += NT) {
            int c  = i / (TY * TX);
            int rm = i - c * (TY * TX);
            int ly = rm / TX, lx = rm - ly * TX;
            int yp = yo + ly, xp = xo + lx;
            S.sp[c][ly][lx] = noise[(((b * NC + c) * HP) + yp) * WP + xp]
                            + img[(((b * NC + c) * NH) + (yp - 1)) * NW + (xp - 1)];
        }
    } else {
        for (int i = tid; i < NC * TY * TX; i += NT) {
            int c  = i / (TY * TX);
            int rm = i - c * (TY * TX);
            int ly = rm / TX, lx = rm - ly * TX;
            int yp = yo + ly, xp = xo + lx;
            float v = 0.f;
            if (yp >= 0 && yp < HP && xp >= 0 && xp < WP) {
                v = noise[(((b * NC + c) * HP) + yp) * WP + xp];
                if (yp >= 1 && yp <= NH && xp >= 1 && xp <= NW)
                    v += img[(((b * NC + c) * NH) + (yp - 1)) * NW + (xp - 1)];
            }
            S.sp[c][ly][lx] = v;
        }
    }
    (void)interior;
    __syncthreads();

    // ---- stage A: img_r + stats, 720 items, manual 2-way unroll ----
    stageA(S, tid, by, bx);
    if (tid + NT < RY * RX) stageA(S, tid + NT, by, bx);
    __syncthreads();

    // ---- stage B: mod, 612 items ----
    stageB(S, tid, by, bx, mix);
    if (tid + NT < MY * MX) stageB(S, tid + NT, by, bx, mix);
    __syncthreads();

    // ---- stage C: final weighted average + blend ----
    float mk[9], den = 0.f;
    #pragma unroll
    for (int k = 0; k < 9; k++) {
        mk[k] = S.sm[ty + k / 3][tx + k % 3];
        den += mk[k];
    }
    float inv_den = __fdividef(1.f, den);
    #pragma unroll
    for (int c = 0; c < NC; c++) {
        float num = 0.f;
        #pragma unroll
        for (int k = 0; k < 9; k++)
            num = fmaf(S.sp[c][ty + 2 + k / 3][tx + 2 + k % 3], mk[k], num);
        float mod = num * inv_den;
        int gi = (((b * NC + c) * NH) + h) * NW + w;
        float r  = re[gi];
        out[gi] = mod * (1.f - r) + img[gi] * r;
    }
}

extern "C" void kernel_launch(void* const* d_in, const int* in_sizes, int n_in,
                              void* d_out, int out_size)
{
    const float* img    = (const float*)d_in[0];
    const float* noise  = (const float*)d_in[1];
    const float* re     = (const float*)d_in[2];
    const int*   sel    = (const int*)d_in[3];
    const int*   mixsel = (const int*)d_in[4];
    float*       out    = (float*)d_out;

    dim3 blk(BX, BY), grd(NW / BX, NH / BY, NB);
    gdfn_fused<<<grd, blk>>>(img, noise, re, sel, mixsel, out);
}